// round 16
// baseline (speedup 1.0000x reference)
#include <cuda_runtime.h>
#include <cstddef>
#include <math.h>

// Problem constants (fixed by the dataset)
#define BATCH 4
#define CH    32
#define HH    120
#define WW    160
#define NXc   160
#define NYc   160
#define NZc   64
#define NVOX  (NXc * NYc * NZc)     // 1,638,400
#define HW    (HH * WW)             // 19,200

#define CH_SPLIT  8                 // threads sharing one voxel-group in pass B
#define CH_PER_T  (CH / CH_SPLIT)   // 4 channels per thread

#define TP_THREADS (BATCH * HW)     // 76,800 transpose threads
#define TP_BLOCKS  (TP_THREADS / 256)          // 300
#define PR_THREADS (BATCH * (NVOX / 4))        // 1,638,400 projection threads
#define PR_BLOCKS  (PR_THREADS / 256)          // 6400

// Channel-transposed features [B][HW][C]: one pixel's 32 channels = exactly
// one 128B cache line -> a single LDG.128 fetches 4 channels.
__device__ __align__(128) float g_tfeat[BATCH * HW * CH];

// Per-voxel gather index as int16 (HW=19200 < 32768), -1 = invalid.
// 13.1 MB -- L2-resident for pass B's re-reads.
__device__ __align__(16) short g_sidx[BATCH * NVOX];

// Round-exact fast division: q = a * rcp.approx(b) with fallback to the IEEE
// correctly-rounded divide whenever q is within tol of a half-integer
// boundary (where rounding could flip), or non-finite. Error of the fast
// path is <= ~2.4e-7*|q|; tol = 1e-5 + 4e-6*|q| gives >= 16x margin, and the
// validity thresholds (-0.5, W-0.5, H-0.5) are themselves half-integers so
// the same test protects the bounds checks. NaN/inf/huge-|q| all fail the
// 'dist > tol' comparison and take the exact path.
__device__ __forceinline__ float div_round_exact(float a, float b, float rcp_b) {
    float q = __fmul_rn(a, rcp_b);
    float fr = q - floorf(q);
    float dist = fabsf(fr - 0.5f);
    float tol = __fmaf_rn(fabsf(q), 4e-6f, 1e-5f);
    if (!(dist > tol)) q = __fdiv_rn(a, b);   // rare (~0.1%) exact fallback
    return q;
}

// ---------------------------------------------------------------------------
// Pass A (merged): blocks [0,300) transpose features to [HW][C]; blocks
// [300, 6700) project one voxel-group each (projection computed ONCE per
// voxel), writing short4 scratch + the valid-mask plane.
//
// Projection math bit-matches the XLA reference (rel_err == 0.0 in R6-R15):
//   world  = coords*vs + origin          (separate mul, add -- NO fma)
//   camera = sum_j P[i,j]*world[j]       (rounded products, ascending adds)
//   u      = camera_x / camera_z         (exact round via fast-path+fallback)
//   px     = round-half-even(u)          (__float2int_rn == jnp.round)
// ---------------------------------------------------------------------------
__global__ __launch_bounds__(256) void prepare_kernel(
    const float* __restrict__ origin,      // [B,3]
    const float* __restrict__ projection,  // [B,3,4]
    const float* __restrict__ features,    // [B,C,H,W]
    const float* __restrict__ voxel_size,  // [1]
    float* __restrict__ out)               // for the valid plane
{
    if (blockIdx.x < TP_BLOCKS) {
        // ---- transpose: [B,C,H,W] -> [B,HW,C] ----
        int t = blockIdx.x * 256 + threadIdx.x;   // < 76,800
        int b = t / HW;
        int p = t - b * HW;
        const float* src = features + (size_t)b * CH * HW + p;
        float* dst = g_tfeat + (size_t)t * CH;
#pragma unroll
        for (int c4 = 0; c4 < CH; c4 += 4) {
            float4 o;
            o.x = __ldg(src + (size_t)(c4 + 0) * HW);
            o.y = __ldg(src + (size_t)(c4 + 1) * HW);
            o.z = __ldg(src + (size_t)(c4 + 2) * HW);
            o.w = __ldg(src + (size_t)(c4 + 3) * HW);
            *reinterpret_cast<float4*>(dst + c4) = o;
        }
        return;
    }

    // ---- projection: one thread per voxel-group ----
    const int groups_per_batch = NVOX / 4;             // 409,600
    int t = (blockIdx.x - TP_BLOCKS) * 256 + threadIdx.x;  // < 1,638,400

    int b  = t / groups_per_batch;
    int r  = t - b * groups_per_batch;
    int v0 = r * 4;
    int k  = v0 & (NZc - 1);
    int ij = v0 >> 6;
    int j  = ij % NYc;
    int i  = ij / NYc;

    const float vs = __ldg(voxel_size);
    const float* P = projection + b * 12;
    float P00 = __ldg(P + 0),  P01 = __ldg(P + 1),  P02 = __ldg(P + 2),  P03 = __ldg(P + 3);
    float P10 = __ldg(P + 4),  P11 = __ldg(P + 5),  P12 = __ldg(P + 6),  P13 = __ldg(P + 7);
    float P20 = __ldg(P + 8),  P21 = __ldg(P + 9),  P22 = __ldg(P + 10), P23 = __ldg(P + 11);
    float ox = __ldg(origin + b * 3 + 0);
    float oy = __ldg(origin + b * 3 + 1);
    float oz = __ldg(origin + b * 3 + 2);

    // world x/y: separately-rounded mul then add (matches coords*vs + origin)
    float wx = __fadd_rn(__fmul_rn((float)i, vs), ox);
    float wy = __fadd_rn(__fmul_rn((float)j, vs), oy);

    short fidx[4];
    float mask[4];
#pragma unroll
    for (int m = 0; m < 4; ++m) {
        float wz = __fadd_rn(__fmul_rn((float)(k + m), vs), oz);

        float cx = __fadd_rn(__fadd_rn(__fadd_rn(__fmul_rn(P00, wx),
                                                  __fmul_rn(P01, wy)),
                                        __fmul_rn(P02, wz)), P03);
        float cy = __fadd_rn(__fadd_rn(__fadd_rn(__fmul_rn(P10, wx),
                                                  __fmul_rn(P11, wy)),
                                        __fmul_rn(P12, wz)), P13);
        float cz = __fadd_rn(__fadd_rn(__fadd_rn(__fmul_rn(P20, wx),
                                                  __fmul_rn(P21, wy)),
                                        __fmul_rn(P22, wz)), P23);

        // One approximate reciprocal serves both coordinates; rounding-exact
        // via boundary-gated fallback (see div_round_exact).
        float rz;
        asm("rcp.approx.f32 %0, %1;" : "=f"(rz) : "f"(cz));
        float u  = div_round_exact(cx, cz, rz);
        float vv = div_round_exact(cy, cz, rz);

        int ipx = __float2int_rn(u);    // round-half-even == jnp.round
        int ipy = __float2int_rn(vv);
        bool ok = (ipx >= 0) && (ipy >= 0) && (ipx < WW) && (ipy < HH) && (cz > 0.0f);
        int cpx = min(max(ipx, 0), WW - 1);
        int cpy = min(max(ipy, 0), HH - 1);
        fidx[m] = ok ? (short)(cpy * WW + cpx) : (short)-1;
        mask[m] = ok ? 1.0f : 0.0f;
    }

    *reinterpret_cast<short4*>(g_sidx + (size_t)b * NVOX + v0) =
        make_short4(fidx[0], fidx[1], fidx[2], fidx[3]);

    float* vout = out + (size_t)BATCH * CH * NVOX + (size_t)b * NVOX + v0;
    __stcs(reinterpret_cast<float4*>(vout),
           make_float4(mask[0], mask[1], mask[2], mask[3]));
}

// ---------------------------------------------------------------------------
// Pass B: scatter (UNCHANGED from R15 -- runs at ~6.0 TB/s of writes, i.e. at
// the HBM write ceiling; do not touch). Thread = (voxel-group, 4-channel
// slice): 1 short4 index load, 4 predicated LDG.128 vector gathers from the
// channel-contiguous [HW][C] features, 4x4 register transpose, 4 __stcs
// float4 coalesced streaming stores.
// ---------------------------------------------------------------------------
__global__ __launch_bounds__(256, 8) void scatter_kernel(
    float* __restrict__ out)               // volume [B,C,NVOX] ++ valid [B,NVOX]
{
    const int groups_per_batch = NVOX / 4;             // 409,600
    int gid = blockIdx.x * blockDim.x + threadIdx.x;
    if (gid >= BATCH * CH_SPLIT * groups_per_batch) return;

    int r  = gid % groups_per_batch;          // voxel group within batch
    int bh = gid / groups_per_batch;          // b * CH_SPLIT + h
    int h  = bh % CH_SPLIT;                   // channel slice
    int b  = bh / CH_SPLIT;
    int v0 = r * 4;

    short4 fs = *reinterpret_cast<const short4*>(g_sidx + (size_t)b * NVOX + v0);
    bool ok0 = fs.x >= 0, ok1 = fs.y >= 0, ok2 = fs.z >= 0, ok3 = fs.w >= 0;

    const int c0 = h * CH_PER_T;
    float* vol = out + ((size_t)b * CH + c0) * NVOX + v0;

    if (ok0 | ok1 | ok2 | ok3) {
        const float* tf = g_tfeat + (size_t)b * HW * CH + c0;
        const float4 zero4 = make_float4(0.f, 0.f, 0.f, 0.f);
        float4 a0 = ok0 ? *reinterpret_cast<const float4*>(tf + (int)fs.x * CH) : zero4;
        float4 a1 = ok1 ? *reinterpret_cast<const float4*>(tf + (int)fs.y * CH) : zero4;
        float4 a2 = ok2 ? *reinterpret_cast<const float4*>(tf + (int)fs.z * CH) : zero4;
        float4 a3 = ok3 ? *reinterpret_cast<const float4*>(tf + (int)fs.w * CH) : zero4;
        __stcs(reinterpret_cast<float4*>(vol + (size_t)0 * NVOX),
               make_float4(a0.x, a1.x, a2.x, a3.x));
        __stcs(reinterpret_cast<float4*>(vol + (size_t)1 * NVOX),
               make_float4(a0.y, a1.y, a2.y, a3.y));
        __stcs(reinterpret_cast<float4*>(vol + (size_t)2 * NVOX),
               make_float4(a0.z, a1.z, a2.z, a3.z));
        __stcs(reinterpret_cast<float4*>(vol + (size_t)3 * NVOX),
               make_float4(a0.w, a1.w, a2.w, a3.w));
    } else {
        const float4 zero = make_float4(0.f, 0.f, 0.f, 0.f);
#pragma unroll
        for (int c = 0; c < CH_PER_T; ++c)
            __stcs(reinterpret_cast<float4*>(vol + (size_t)c * NVOX), zero);
    }
}

extern "C" void kernel_launch(void* const* d_in, const int* in_sizes, int n_in,
                              void* d_out, int out_size)
{
    // Expected metadata order: origin[12], projection[48], features[2457600],
    // voxel_size[1]. Identify tensors by unique sizes as a guard.
    const float* origin     = (const float*)d_in[0];
    const float* projection = (const float*)d_in[1];
    const float* features   = (const float*)d_in[2];
    const float* voxel_size = (const float*)d_in[3];
    for (int t = 0; t < n_in; ++t) {
        if (in_sizes[t] == BATCH * CH * HH * WW) features   = (const float*)d_in[t];
        else if (in_sizes[t] == BATCH * 12)      projection = (const float*)d_in[t];
        else if (in_sizes[t] == BATCH * 3)       origin     = (const float*)d_in[t];
    }
    float* out = (float*)d_out;

    // Pass A: feature transpose + projections + valid plane (merged grid).
    prepare_kernel<<<TP_BLOCKS + PR_BLOCKS, 256>>>(origin, projection,
                                                   features, voxel_size, out);

    // Pass B: vector-gather + scatter of the feature volume.
    const int b_threads = BATCH * CH_SPLIT * (NVOX / 4);      // 13,107,200
    scatter_kernel<<<(b_threads + 255) / 256, 256>>>(out);
}

// round 17
// speedup vs baseline: 1.1630x; 1.1630x over previous
#include <cuda_runtime.h>
#include <cstddef>

// Problem constants (fixed by the dataset)
#define BATCH 4
#define CH    32
#define HH    120
#define WW    160
#define NXc   160
#define NYc   160
#define NZc   64
#define NVOX  (NXc * NYc * NZc)     // 1,638,400
#define HW    (HH * WW)             // 19,200

#define TP_THREADS (BATCH * HW)     // 76,800 transpose threads
#define TP_BLOCKS  (TP_THREADS / 256)          // 300
#define PR_THREADS (BATCH * (NVOX / 4))        // 1,638,400 projection threads
#define PR_BLOCKS  (PR_THREADS / 256)          // 6400

// Channel-transposed features [B][HW][C]: one pixel's 32 channels = exactly
// one 128B cache line.
__device__ __align__(128) float g_tfeat[BATCH * HW * CH];

// Per-voxel gather index as int16 (HW=19200 < 32768), -1 = invalid.
// 13.1 MB -- L2-resident for pass B's re-reads.
__device__ __align__(16) short g_sidx[BATCH * NVOX];

// ---------------------------------------------------------------------------
// Pass A (merged): blocks [0,300) transpose features to [HW][C]; blocks
// [300, 6700) project one voxel-group each (projection computed ONCE per
// voxel), writing short4 scratch + the valid-mask plane.  (R16 showed the
// rcp fast-path is neutral here -- pass A is traffic/launch bound -- so this
// is the proven R15 version with plain IEEE divides.)
//
// Projection math bit-matches the XLA reference (rel_err == 0.0 in R6-R16):
//   world  = coords*vs + origin          (separate mul, add -- NO fma)
//   camera = sum_j P[i,j]*world[j]       (rounded products, ascending adds)
//   u      = camera_x / camera_z         (IEEE correctly-rounded divide)
//   px     = round-half-even(u)          (__float2int_rn == jnp.round)
// ---------------------------------------------------------------------------
__global__ __launch_bounds__(256) void prepare_kernel(
    const float* __restrict__ origin,      // [B,3]
    const float* __restrict__ projection,  // [B,3,4]
    const float* __restrict__ features,    // [B,C,H,W]
    const float* __restrict__ voxel_size,  // [1]
    float* __restrict__ out)               // for the valid plane
{
    if (blockIdx.x < TP_BLOCKS) {
        // ---- transpose: [B,C,H,W] -> [B,HW,C] ----
        int t = blockIdx.x * 256 + threadIdx.x;   // < 76,800
        int b = t / HW;
        int p = t - b * HW;
        const float* src = features + (size_t)b * CH * HW + p;
        float* dst = g_tfeat + (size_t)t * CH;
#pragma unroll
        for (int c4 = 0; c4 < CH; c4 += 4) {
            float4 o;
            o.x = __ldg(src + (size_t)(c4 + 0) * HW);
            o.y = __ldg(src + (size_t)(c4 + 1) * HW);
            o.z = __ldg(src + (size_t)(c4 + 2) * HW);
            o.w = __ldg(src + (size_t)(c4 + 3) * HW);
            *reinterpret_cast<float4*>(dst + c4) = o;
        }
        return;
    }

    // ---- projection: one thread per voxel-group ----
    const int groups_per_batch = NVOX / 4;             // 409,600
    int t = (blockIdx.x - TP_BLOCKS) * 256 + threadIdx.x;  // < 1,638,400

    int b  = t / groups_per_batch;
    int r  = t - b * groups_per_batch;
    int v0 = r * 4;
    int k  = v0 & (NZc - 1);
    int ij = v0 >> 6;
    int j  = ij % NYc;
    int i  = ij / NYc;

    const float vs = __ldg(voxel_size);
    const float* P = projection + b * 12;
    float P00 = __ldg(P + 0),  P01 = __ldg(P + 1),  P02 = __ldg(P + 2),  P03 = __ldg(P + 3);
    float P10 = __ldg(P + 4),  P11 = __ldg(P + 5),  P12 = __ldg(P + 6),  P13 = __ldg(P + 7);
    float P20 = __ldg(P + 8),  P21 = __ldg(P + 9),  P22 = __ldg(P + 10), P23 = __ldg(P + 11);
    float ox = __ldg(origin + b * 3 + 0);
    float oy = __ldg(origin + b * 3 + 1);
    float oz = __ldg(origin + b * 3 + 2);

    // world x/y: separately-rounded mul then add (matches coords*vs + origin)
    float wx = __fadd_rn(__fmul_rn((float)i, vs), ox);
    float wy = __fadd_rn(__fmul_rn((float)j, vs), oy);

    short fidx[4];
    float mask[4];
#pragma unroll
    for (int m = 0; m < 4; ++m) {
        float wz = __fadd_rn(__fmul_rn((float)(k + m), vs), oz);

        float cx = __fadd_rn(__fadd_rn(__fadd_rn(__fmul_rn(P00, wx),
                                                  __fmul_rn(P01, wy)),
                                        __fmul_rn(P02, wz)), P03);
        float cy = __fadd_rn(__fadd_rn(__fadd_rn(__fmul_rn(P10, wx),
                                                  __fmul_rn(P11, wy)),
                                        __fmul_rn(P12, wz)), P13);
        float cz = __fadd_rn(__fadd_rn(__fadd_rn(__fmul_rn(P20, wx),
                                                  __fmul_rn(P21, wy)),
                                        __fmul_rn(P22, wz)), P23);

        float u  = __fdiv_rn(cx, cz);   // IEEE rn divide
        float vv = __fdiv_rn(cy, cz);
        int ipx = __float2int_rn(u);    // round-half-even == jnp.round
        int ipy = __float2int_rn(vv);
        bool ok = (ipx >= 0) && (ipy >= 0) && (ipx < WW) && (ipy < HH) && (cz > 0.0f);
        int cpx = min(max(ipx, 0), WW - 1);
        int cpy = min(max(ipy, 0), HH - 1);
        fidx[m] = ok ? (short)(cpy * WW + cpx) : (short)-1;
        mask[m] = ok ? 1.0f : 0.0f;
    }

    *reinterpret_cast<short4*>(g_sidx + (size_t)b * NVOX + v0) =
        make_short4(fidx[0], fidx[1], fidx[2], fidx[3]);

    float* vout = out + (size_t)BATCH * CH * NVOX + (size_t)b * NVOX + v0;
    __stcs(reinterpret_cast<float4*>(vout),
           make_float4(mask[0], mask[1], mask[2], mask[3]));
}

// ---------------------------------------------------------------------------
// Pass B: warp-cooperative scatter. One warp owns 32 consecutive voxels.
//
//  Fetch (8 warp-LDG.128): lane l -> voxel it*4+(l>>3), chunk l&7.
//    8 lanes cooperate on each pixel's 128B channel line -> 1 wavefront per
//    line (R15 scatter re-touched every line 8x across the channel-slice
//    warps: ~880 gather wavefronts per 128 voxels x 32ch vs 128 store
//    wavefronts -> L1=85%). Staged into smem (row stride 33 floats: fetch
//    STS.32 banks (row+4*chunk+e)%32 all-distinct; read LDS.32 banks
//    (4*(l&7)+r+cb+(l>>3))%32 all-distinct -> conflict-free both ways).
//  Store (8 warp-STG.128): lane l -> group l&7, channel cb+(l>>3); each
//    4-channel quad stores 4x128B fully-coalesced streaming.
//  All-invalid warps (ballot) skip fetch/smem and stream zeros.
// ---------------------------------------------------------------------------
#define SM_STRIDE 33
__global__ __launch_bounds__(256) void scatter_kernel(
    float* __restrict__ out)               // volume [B,C,NVOX] ++ valid [B,NVOX]
{
    __shared__ float sm[8][32 * SM_STRIDE];   // 33,792 B

    int wid  = threadIdx.x >> 5;
    int lane = threadIdx.x & 31;
    int gw = blockIdx.x * 8 + wid;                 // global warp id
    const int warps_per_batch = NVOX / 32;         // 51,200
    int b  = gw / warps_per_batch;
    int rw = gw - b * warps_per_batch;
    int v0 = rw * 32;                              // 32 consecutive voxels

    int s = (int)g_sidx[(size_t)b * NVOX + v0 + lane];   // my voxel's pixel (-1 invalid)
    unsigned vm = __ballot_sync(0xffffffffu, s >= 0);

    float* vol = out + (size_t)b * CH * NVOX + v0;
    int cs = lane >> 3;            // channel offset within quad
    int vg = (lane & 7) * 4;       // voxel offset within the 32

    if (vm == 0u) {
        const float4 zero = make_float4(0.f, 0.f, 0.f, 0.f);
#pragma unroll
        for (int cb = 0; cb < CH; cb += 4)
            __stcs(reinterpret_cast<float4*>(vol + (size_t)(cb + cs) * NVOX + vg), zero);
        return;
    }

    const float* tf = g_tfeat + (size_t)b * HW * CH;
    float* sw = sm[wid];

#pragma unroll
    for (int it = 0; it < 8; ++it) {
        int row = it * 4 + (lane >> 3);                       // voxel 0..31
        int p = __shfl_sync(0xffffffffu, s, row);             // its pixel
        int chunk = lane & 7;                                  // 16B chunk 0..7
        float4 o = make_float4(0.f, 0.f, 0.f, 0.f);
        if (p >= 0)
            o = *reinterpret_cast<const float4*>(tf + (size_t)p * CH + chunk * 4);
        int base = row * SM_STRIDE + chunk * 4;
        sw[base + 0] = o.x;   // scalar STS: conflict-free, no 16B-align need
        sw[base + 1] = o.y;
        sw[base + 2] = o.z;
        sw[base + 3] = o.w;
    }
    __syncwarp();

#pragma unroll
    for (int cb = 0; cb < CH; cb += 4) {
        int c = cb + cs;
        float4 o;
        o.x = sw[(vg + 0) * SM_STRIDE + c];
        o.y = sw[(vg + 1) * SM_STRIDE + c];
        o.z = sw[(vg + 2) * SM_STRIDE + c];
        o.w = sw[(vg + 3) * SM_STRIDE + c];
        __stcs(reinterpret_cast<float4*>(vol + (size_t)c * NVOX + vg), o);
    }
}

extern "C" void kernel_launch(void* const* d_in, const int* in_sizes, int n_in,
                              void* d_out, int out_size)
{
    // Expected metadata order: origin[12], projection[48], features[2457600],
    // voxel_size[1]. Identify tensors by unique sizes as a guard.
    const float* origin     = (const float*)d_in[0];
    const float* projection = (const float*)d_in[1];
    const float* features   = (const float*)d_in[2];
    const float* voxel_size = (const float*)d_in[3];
    for (int t = 0; t < n_in; ++t) {
        if (in_sizes[t] == BATCH * CH * HH * WW) features   = (const float*)d_in[t];
        else if (in_sizes[t] == BATCH * 12)      projection = (const float*)d_in[t];
        else if (in_sizes[t] == BATCH * 3)       origin     = (const float*)d_in[t];
    }
    float* out = (float*)d_out;

    // Pass A: feature transpose + projections + valid plane (merged grid).
    prepare_kernel<<<TP_BLOCKS + PR_BLOCKS, 256>>>(origin, projection,
                                                   features, voxel_size, out);

    // Pass B: warp-cooperative scatter. 204,800 warps / 8 per block.
    const int b_blocks = (BATCH * (NVOX / 32)) / 8;           // 25,600
    scatter_kernel<<<b_blocks, 256>>>(out);
}